// round 1
// baseline (speedup 1.0000x reference)
#include <cuda_runtime.h>

#define CAM_FL  540.0f
#define HALF_W  320.0f
#define HALF_H  240.0f
#define CAM_W   640
#define CAM_H   480

__global__ void zero_kernel(float4* __restrict__ out, int n4) {
    int i = blockIdx.x * blockDim.x + threadIdx.x;
    if (i < n4) out[i] = make_float4(0.f, 0.f, 0.f, 0.f);
}

__global__ __launch_bounds__(256) void proj_kernel(
    const float* __restrict__ locs,
    const float* __restrict__ pose,
    const float* __restrict__ rotq,
    const float* __restrict__ depth,
    float* __restrict__ out,
    int N)
{
    const int i = blockIdx.x * blockDim.x + threadIdx.x;
    const int b = blockIdx.y;
    if (i >= N) return;

    // --- quaternion (normalized, conjugated) -> rotation matrix ---
    float qx = __ldg(rotq + b * 4 + 0);
    float qy = __ldg(rotq + b * 4 + 1);
    float qz = __ldg(rotq + b * 4 + 2);
    float qw = __ldg(rotq + b * 4 + 3);
    float inv = rsqrtf(qx * qx + qy * qy + qz * qz + qw * qw);
    qx = -qx * inv; qy = -qy * inv; qz = -qz * inv; qw = qw * inv;

    const float qx2 = qx * qx, qy2 = qy * qy, qz2 = qz * qz;
    const float qxqy = qx * qy, qxqz = qx * qz, qxqw = qx * qw;
    const float qyqz = qy * qz, qyqw = qy * qw, qzqw = qz * qw;
    // R[i][j] per reference _rot_from_quat; einsum does p_new[j] = sum_i p[i]*R[i][j]
    const float r00 = 1.f - 2.f * qy2 - 2.f * qz2;
    const float r10 = 2.f * qxqy - 2.f * qzqw;
    const float r20 = 2.f * qxqz + 2.f * qyqw;
    const float r01 = 2.f * qxqy + 2.f * qzqw;
    const float r11 = 1.f - 2.f * qx2 - 2.f * qz2;
    const float r21 = 2.f * qyqz - 2.f * qxqw;
    const float r02 = 2.f * qxqz - 2.f * qyqw;
    const float r12 = 2.f * qyqz + 2.f * qxqw;
    const float r22 = 1.f - 2.f * qx2 - 2.f * qy2;

    // --- load particle, transform to camera frame ---
    const float* lp = locs + ((long long)b * N + i) * 3;
    const float p0 = lp[0] - __ldg(pose + b * 3 + 0);
    const float p1 = lp[1] - __ldg(pose + b * 3 + 1);
    const float p2 = lp[2] - __ldg(pose + b * 3 + 2);

    const float x = p0 * r00 + p1 * r10 + p2 * r20;
    const float y = p0 * r01 + p1 * r11 + p2 * r21;
    const float z = p0 * r02 + p1 * r12 + p2 * r22;

    if (!(z > 0.f)) return;                  // zb > 0 required for any validity

    const float invz = __frcp_rn(z);
    const float px = x * invz * CAM_FL + HALF_W;
    const float py = y * invz * CAM_FL + HALF_H;

    // 5x5 window must intersect the image: floor(px) in [-2, 641], floor(py) in [-2, 481].
    // Float-domain test (also rejects the saturating-huge-px cases, whose weights are 0).
    if (!(px >= -2.f && px < 642.f && py >= -2.f && py < 482.f)) return;

    const float fx = floorf(px), fy = floorf(py);
    const int jb = (int)fx - 2;
    const int ib = (int)fy - 2;
    const float dxb = fx - px;               // in [-1, 0]
    const float dyb = fy - py;

    // separable Gaussian weights
    float wx[5], wy[5];
#pragma unroll
    for (int k = 0; k < 5; k++) {
        const float dx = dxb + (float)(k - 2);
        const float dy = dyb + (float)(k - 2);
        wx[k] = __expf(-0.5f * dx * dx);
        wy[k] = __expf(-0.5f * dy * dy);
    }

    const float* dimg = depth + (long long)b * CAM_H * CAM_W;
    float*       oimg = out   + (long long)b * CAM_H * CAM_W;

#pragma unroll
    for (int ii = 0; ii < 5; ii++) {
        const int yy = ib + ii;
        if (yy < 0 || yy >= CAM_H) continue;
        const int rowoff = yy * CAM_W;
#pragma unroll
        for (int jj = 0; jj < 5; jj++) {
            const int xx = jb + jj;
            if (xx < 0 || xx >= CAM_W) continue;
            const float d = __ldg(dimg + rowoff + xx);
            if (z <= d) {
                atomicAdd(oimg + rowoff + xx, wy[ii] * wx[jj]);
            }
        }
    }
}

extern "C" void kernel_launch(void* const* d_in, const int* in_sizes, int n_in,
                              void* d_out, int out_size) {
    const float* locs  = (const float*)d_in[0];
    const float* pose  = (const float*)d_in[1];
    const float* rotq  = (const float*)d_in[2];
    const float* depth = (const float*)d_in[3];
    float* out = (float*)d_out;

    const int B = in_sizes[1] / 3;           // 4
    const int N = in_sizes[0] / (3 * B);     // 200000

    const int n4 = out_size / 4;             // out_size divisible by 4 (4*480*640)
    zero_kernel<<<(n4 + 255) / 256, 256>>>((float4*)d_out, n4);

    dim3 grid((N + 255) / 256, B);
    proj_kernel<<<grid, 256>>>(locs, pose, rotq, depth, out, N);
}

// round 2
// speedup vs baseline: 1.4848x; 1.4848x over previous
#include <cuda_runtime.h>

#define CAM_FL  540.0f
#define HALF_W  320.0f
#define HALF_H  240.0f
#define CAM_W   640
#define CAM_H   480
#define PB      512      // particles per block
#define TPB     256      // threads per block

__global__ __launch_bounds__(TPB) void proj_kernel(
    const float* __restrict__ locs,
    const float* __restrict__ pose,
    const float* __restrict__ rotq,
    const float* __restrict__ depth,
    float* __restrict__ out,
    int N)
{
    __shared__ int   s_ib[PB];
    __shared__ int   s_jb[PB];
    __shared__ float s_z[PB];
    __shared__ float s_w[PB][10];   // [0..4]=wx, [5..9]=wy
    __shared__ int   s_cnt;

    const int tid  = threadIdx.x;
    const int b    = blockIdx.y;
    const int base = blockIdx.x * PB;

    if (tid == 0) s_cnt = 0;

    // --- quaternion (normalized, conjugated) -> rotation matrix (redundant per thread, cheap) ---
    float qx = __ldg(rotq + b * 4 + 0);
    float qy = __ldg(rotq + b * 4 + 1);
    float qz = __ldg(rotq + b * 4 + 2);
    float qw = __ldg(rotq + b * 4 + 3);
    float inv = rsqrtf(qx * qx + qy * qy + qz * qz + qw * qw);
    qx = -qx * inv; qy = -qy * inv; qz = -qz * inv; qw = qw * inv;

    const float qx2 = qx * qx, qy2 = qy * qy, qz2 = qz * qz;
    const float qxqy = qx * qy, qxqz = qx * qz, qxqw = qx * qw;
    const float qyqz = qy * qz, qyqw = qy * qw, qzqw = qz * qw;
    const float r00 = 1.f - 2.f * qy2 - 2.f * qz2;
    const float r10 = 2.f * qxqy - 2.f * qzqw;
    const float r20 = 2.f * qxqz + 2.f * qyqw;
    const float r01 = 2.f * qxqy + 2.f * qzqw;
    const float r11 = 1.f - 2.f * qx2 - 2.f * qz2;
    const float r21 = 2.f * qyqz - 2.f * qxqw;
    const float r02 = 2.f * qxqz - 2.f * qyqw;
    const float r12 = 2.f * qyqz + 2.f * qxqw;
    const float r22 = 1.f - 2.f * qx2 - 2.f * qy2;

    const float cx = __ldg(pose + b * 3 + 0);
    const float cy = __ldg(pose + b * 3 + 1);
    const float cz = __ldg(pose + b * 3 + 2);

    __syncthreads();   // s_cnt init visible before compaction atomics

    // ---------------- Phase 1: project + compact survivors into smem ----------------
    const float C1 = 0.60653066f;   // exp(-0.5)
    const float C2 = 0.13533528f;   // exp(-2)

#pragma unroll
    for (int half = 0; half < 2; half++) {
        const int i = base + half * TPB + tid;
        bool ok = false;
        float z = 0.f, px = 0.f, py = 0.f;
        if (i < N) {
            const float* lp = locs + ((long long)b * N + i) * 3;
            const float p0 = lp[0] - cx;
            const float p1 = lp[1] - cy;
            const float p2 = lp[2] - cz;
            const float x = p0 * r00 + p1 * r10 + p2 * r20;
            const float y = p0 * r01 + p1 * r11 + p2 * r21;
            z = p0 * r02 + p1 * r12 + p2 * r22;
            if (z > 0.f) {
                const float invz = __frcp_rn(z);
                px = x * invz * CAM_FL + HALF_W;
                py = y * invz * CAM_FL + HALF_H;
                // 5x5 window intersects image iff floor(px) in [-2,641], floor(py) in [-2,481]
                ok = (px >= -2.f && px < 642.f && py >= -2.f && py < 482.f);
            }
        }

        // warp-aggregated compaction index
        const unsigned m = __ballot_sync(0xffffffffu, ok);
        int idx = 0;
        if (m) {
            const int lane = tid & 31;
            const int lead = __ffs(m) - 1;
            int wbase = 0;
            if (lane == lead) wbase = atomicAdd(&s_cnt, __popc(m));
            wbase = __shfl_sync(0xffffffffu, wbase, lead);
            idx = wbase + __popc(m & ((1u << lane) - 1u));
        }

        if (ok) {
            const float fx = floorf(px), fy = floorf(py);
            s_jb[idx] = (int)fx - 2;
            s_ib[idx] = (int)fy - 2;
            s_z[idx]  = z;

            // separable Gaussian, factorized: exp(-0.5(u+o)^2) = a * e^{-o u} * exp(-o^2/2)
            const float u = fx - px;          // in [-1, 0]
            const float v = fy - py;

            const float ax  = __expf(-0.5f * u * u);
            const float ex  = __expf(-u);
            const float exi = __frcp_rn(ex);
            s_w[idx][0] = ax * exi * exi * C2;
            s_w[idx][1] = ax * exi * C1;
            s_w[idx][2] = ax;
            s_w[idx][3] = ax * ex * C1;
            s_w[idx][4] = ax * ex * ex * C2;

            const float ay  = __expf(-0.5f * v * v);
            const float ey  = __expf(-v);
            const float eyi = __frcp_rn(ey);
            s_w[idx][5] = ay * eyi * eyi * C2;
            s_w[idx][6] = ay * eyi * C1;
            s_w[idx][7] = ay;
            s_w[idx][8] = ay * ey * C1;
            s_w[idx][9] = ay * ey * ey * C2;
        }
    }

    __syncthreads();

    // ---------------- Phase 2: cooperative splat, full lane density ----------------
    const int cnt   = s_cnt;
    const int total = cnt * 25;
    const float* dimg = depth + b * (CAM_H * CAM_W);
    float*       oimg = out   + b * (CAM_H * CAM_W);

    for (int t = tid; t < total; t += TPB) {
        const int s  = t / 25;
        const int k  = t - s * 25;
        const int ii = k / 5;
        const int jj = k - ii * 5;

        const int yy = s_ib[s] + ii;
        const int xx = s_jb[s] + jj;
        if (yy >= 0 && yy < CAM_H && xx >= 0 && xx < CAM_W) {
            const int o = yy * CAM_W + xx;
            const float d = __ldg(dimg + o);
            const float z = s_z[s];
            if (z <= d) {
                atomicAdd(oimg + o, s_w[s][5 + ii] * s_w[s][jj]);
            }
        }
    }
}

extern "C" void kernel_launch(void* const* d_in, const int* in_sizes, int n_in,
                              void* d_out, int out_size) {
    const float* locs  = (const float*)d_in[0];
    const float* pose  = (const float*)d_in[1];
    const float* rotq  = (const float*)d_in[2];
    const float* depth = (const float*)d_in[3];
    float* out = (float*)d_out;

    const int B = in_sizes[1] / 3;           // 4
    const int N = in_sizes[0] / (3 * B);     // 200000

    cudaMemsetAsync(d_out, 0, (size_t)out_size * sizeof(float), 0);

    dim3 grid((N + PB - 1) / PB, B);
    proj_kernel<<<grid, TPB>>>(locs, pose, rotq, depth, out, N);
}